// round 6
// baseline (speedup 1.0000x reference)
#include <cuda_runtime.h>
#include <cstdint>

// out = IFFT( D .* FFT( A .* x ) ) per row, C = 4096, complex as (re,im) float pairs.
// A, D scale re/im independently (elementwise).
//
// 128 threads per row; each thread carries TWO sub-FFT lanes as plain scalar
// floats (rA/iA, rB/iB). Complex multiplies in 4-instruction fma form.
// 4096 = 16^3: three radix-16 register stages; two shared exchanges per
// direction as float4{reA,reB,imA,imB} (16B STS/LDS, conflict-free strides
// 129 / 9). Twiddles via one __sincosf + odd/even power chains per stage.
// __launch_bounds__(128, 5) caps regs at 102 -> 5 CTAs/SM (20 warps).

#define REV(c) ((((c) & 3) << 2) | ((c) >> 2))

// complex multiply, 4 instrs: r' = fma(r,wr,-(i*wi)); i' = fma(r,wi,i*wr)
__device__ __forceinline__ void cmul(float& r, float& i, float wr, float wi){
    float t = i * wi;
    float u = i * wr;
    float nr = fmaf(r, wr, -t);
    i = fmaf(r, wi, u);
    r = nr;
}

// multiply by -i (DIR<0) / +i (DIR>0)
template<int DIR> __device__ __forceinline__ void mulj(float& r, float& i){
    float t = r;
    if (DIR < 0){ r = i;  i = -t; }
    else        { r = -i; i = t;  }
}
// constant twiddle: forward (cr, ci_f); inverse conjugate
template<int DIR> __device__ __forceinline__ void cmulc(float& r, float& i, float cr, float ci_f){
    cmul(r, i, cr, (DIR < 0) ? ci_f : -ci_f);
}

#define TC1 0.92387953251128674f
#define TS1 0.38268343236508978f
#define TC2 0.70710678118654752f

template<int DIR>
__device__ __forceinline__ void fft4s(float& r0, float& i0, float& r1, float& i1,
                                      float& r2, float& i2, float& r3, float& i3){
    float t0r = r0 + r2, t0i = i0 + i2;
    float t1r = r0 - r2, t1i = i0 - i2;
    float t2r = r1 + r3, t2i = i1 + i3;
    float t3r, t3i;
    if (DIR < 0){ t3r = i1 - i3; t3i = r3 - r1; }
    else        { t3r = i3 - i1; t3i = r1 - r3; }
    r0 = t0r + t2r; i0 = t0i + t2i;
    r2 = t0r - t2r; i2 = t0i - t2i;
    r1 = t1r + t3r; i1 = t1i + t3i;
    r3 = t1r - t3r; i3 = t1i - t3i;
}

// 16-point DFT, natural slots in -> output c at slot REV(c)
template<int DIR>
__device__ __forceinline__ void fft16_nat(float r[16], float i[16]){
    fft4s<DIR>(r[0],i[0], r[4],i[4], r[8], i[8],  r[12],i[12]);
    fft4s<DIR>(r[1],i[1], r[5],i[5], r[9], i[9],  r[13],i[13]);
    fft4s<DIR>(r[2],i[2], r[6],i[6], r[10],i[10], r[14],i[14]);
    fft4s<DIR>(r[3],i[3], r[7],i[7], r[11],i[11], r[15],i[15]);
    cmulc<DIR>(r[5], i[5],  TC1, -TS1);
    cmulc<DIR>(r[9], i[9],  TC2, -TC2);
    cmulc<DIR>(r[13],i[13], TS1, -TC1);
    cmulc<DIR>(r[6], i[6],  TC2, -TC2);
    mulj<DIR>(r[10],i[10]);
    cmulc<DIR>(r[14],i[14],-TC2, -TC2);
    cmulc<DIR>(r[7], i[7],  TS1, -TC1);
    cmulc<DIR>(r[11],i[11],-TC2, -TC2);
    cmulc<DIR>(r[15],i[15],-TC1,  TS1);
    fft4s<DIR>(r[0], i[0],  r[1], i[1],  r[2], i[2],  r[3], i[3]);
    fft4s<DIR>(r[4], i[4],  r[5], i[5],  r[6], i[6],  r[7], i[7]);
    fft4s<DIR>(r[8], i[8],  r[9], i[9],  r[10],i[10], r[11],i[11]);
    fft4s<DIR>(r[12],i[12], r[13],i[13], r[14],i[14], r[15],i[15]);
}

// 16-point DFT, input logical a at slot REV(a) -> natural output slots
template<int DIR>
__device__ __forceinline__ void fft16_rev(float r[16], float i[16]){
    fft4s<DIR>(r[0], i[0],  r[1], i[1],  r[2], i[2],  r[3], i[3]);
    fft4s<DIR>(r[4], i[4],  r[5], i[5],  r[6], i[6],  r[7], i[7]);
    fft4s<DIR>(r[8], i[8],  r[9], i[9],  r[10],i[10], r[11],i[11]);
    fft4s<DIR>(r[12],i[12], r[13],i[13], r[14],i[14], r[15],i[15]);
    cmulc<DIR>(r[5], i[5],  TC1, -TS1);
    cmulc<DIR>(r[6], i[6],  TC2, -TC2);
    cmulc<DIR>(r[7], i[7],  TS1, -TC1);
    cmulc<DIR>(r[9], i[9],  TC2, -TC2);
    mulj<DIR>(r[10],i[10]);
    cmulc<DIR>(r[11],i[11],-TC2, -TC2);
    cmulc<DIR>(r[13],i[13], TS1, -TC1);
    cmulc<DIR>(r[14],i[14],-TC2, -TC2);
    cmulc<DIR>(r[15],i[15],-TC1,  TS1);
    fft4s<DIR>(r[0],i[0], r[4],i[4], r[8], i[8],  r[12],i[12]);
    fft4s<DIR>(r[1],i[1], r[5],i[5], r[9], i[9],  r[13],i[13]);
    fft4s<DIR>(r[2],i[2], r[6],i[6], r[10],i[10], r[14],i[14]);
    fft4s<DIR>(r[3],i[3], r[7],i[7], r[11],i[11], r[15],i[15]);
}

// apply w^k to v[slot(k)], k=1..15; w = e^{DIR*i*theta}
template<int DIR, int RV>
__device__ __forceinline__ void twiddle_stage(float r[16], float i[16], float theta){
    float sn, cs;
    __sincosf(theta, &sn, &cs);
    if (DIR < 0) sn = -sn;
    float w2r = fmaf(cs, cs, -(sn * sn));
    float w2i = 2.0f * cs * sn;
    float por = cs,  poi = sn;    // odd powers
    float per = w2r, pei = w2i;   // even powers
    #pragma unroll
    for (int k = 1; k < 16; ++k){
        const int slot = RV ? REV(k) : k;
        if (k & 1){
            cmul(r[slot], i[slot], por, poi);
            if (k + 2 < 16) cmul(por, poi, w2r, w2i);
        } else {
            cmul(r[slot], i[slot], per, pei);
            if (k + 2 < 16) cmul(per, pei, w2r, w2i);
        }
    }
}

#define S1R 129   // entry stride (16B units); conflict-free for 128-bit LDS/STS
#define S2R 9
#define D4096 1.5339807878856412e-3f   // 2*pi/4096
#define D256  2.4543692606170259e-2f   // 2*pi/256
#define INV_N (1.0f / 4096.0f)

__global__ void __launch_bounds__(128, 5) afdf_fft6_kernel(
    const float4* __restrict__ x4,
    const float4* __restrict__ A4,
    const float2* __restrict__ D2,
    float2* __restrict__ out2)
{
    // shared scratch, reused: S1 = 16 rows x 129 entries; S2 = 256 rows x 9 entries
    // each entry = float4 {reA, reB, imA, imB}
    __shared__ float4 sb[256 * S2R];   // 2304 * 16B = 36,864 B

    const int t  = threadIdx.x;        // 0..127
    const int c1 = t & 15;
    const int u  = t >> 4;             // 0..7
    const size_t rb4 = (size_t)blockIdx.x * 2048;   // row base in float4 units
    const size_t rb2 = (size_t)blockIdx.x * 4096;   // row base in float2 units

    float rA[16], iA[16], rB[16], iB[16];

    // ---- load x, apply A; lanes = points m = (2t, 2t+1) ----
    #pragma unroll
    for (int a = 0; a < 16; ++a){
        const float4 xv = x4[rb4 + 128 * a + t];
        const float4 av = A4[128 * a + t];
        rA[a] = xv.x * av.x;  iA[a] = xv.y * av.y;
        rB[a] = xv.z * av.z;  iB[a] = xv.w * av.w;
    }

    // ================= forward =================
    fft16_nat<-1>(rA, iA);
    fft16_nat<-1>(rB, iB);
    twiddle_stage<-1, 1>(rA, iA, (float)(2*t)     * D4096);
    twiddle_stage<-1, 1>(rB, iB, (float)(2*t + 1) * D4096);
    #pragma unroll
    for (int c = 0; c < 16; ++c){
        const int s = REV(c);
        sb[c * S1R + t] = make_float4(rA[s], rB[s], iA[s], iB[s]);
    }
    __syncthreads();
    // stage 2: lanes = (b2 = 2u, 2u+1), iterate a2
    #pragma unroll
    for (int a2 = 0; a2 < 16; ++a2){
        const float4 v = sb[c1 * S1R + 8 * a2 + u];
        rA[a2] = v.x; rB[a2] = v.y; iA[a2] = v.z; iB[a2] = v.w;
    }
    fft16_nat<-1>(rA, iA);
    fft16_nat<-1>(rB, iB);
    twiddle_stage<-1, 1>(rA, iA, (float)(2*u)     * D256);
    twiddle_stage<-1, 1>(rB, iB, (float)(2*u + 1) * D256);
    __syncthreads();
    #pragma unroll
    for (int c2 = 0; c2 < 16; ++c2){
        const int s = REV(c2);
        sb[(16 * c2 + c1) * S2R + u] = make_float4(rA[s], rB[s], iA[s], iB[s]);
    }
    __syncthreads();
    // stage 3: lanes = (r = t, t+128); stored pairs along b2 -> rename
    #pragma unroll
    for (int uu = 0; uu < 8; ++uu){
        const float4 L = sb[t * S2R + uu];
        const float4 H = sb[(t + 128) * S2R + uu];
        rA[2*uu]   = L.x; iA[2*uu]   = L.z; rB[2*uu]   = H.x; iB[2*uu]   = H.z;
        rA[2*uu+1] = L.y; iA[2*uu+1] = L.w; rB[2*uu+1] = H.y; iB[2*uu+1] = H.w;
    }
    fft16_nat<-1>(rA, iA);
    fft16_nat<-1>(rB, iB);      // F[256*d2 + r] at slot REV(d2)

    // ---- D scale (1/N folded), freq = 256*d2 + (t | t+128) ----
    #pragma unroll
    for (int d2 = 0; d2 < 16; ++d2){
        const float2 da = D2[256 * d2 + t];
        const float2 db = D2[256 * d2 + t + 128];
        const int s = REV(d2);
        rA[s] *= da.x * INV_N;  iA[s] *= da.y * INV_N;
        rB[s] *= db.x * INV_N;  iB[s] *= db.y * INV_N;
    }
    __syncthreads();   // stage-3 reads complete before buffer reuse

    // ================= inverse =================
    fft16_rev<1>(rA, iA);
    fft16_rev<1>(rB, iB);
    twiddle_stage<1, 0>(rA, iA, (float)t * D4096);
    twiddle_stage<1, 0>(rB, iB, (float)(t + 128) * D4096);
    #pragma unroll
    for (int c = 0; c < 16; ++c){
        sb[c * S1R + t] = make_float4(rA[c], rB[c], iA[c], iB[c]);  // lanes (r=t, t+128)
    }
    __syncthreads();
    // stage 2 inv: lanes = (b2 = u, u+8); rename from (r, r+128) pairs
    #pragma unroll
    for (int aa = 0; aa < 8; ++aa){
        const float4 L = sb[c1 * S1R + 16 * aa + u];
        const float4 H = sb[c1 * S1R + 16 * aa + u + 8];
        rA[aa]   = L.x; iA[aa]   = L.z; rB[aa]   = H.x; iB[aa]   = H.z;
        rA[aa+8] = L.y; iA[aa+8] = L.w; rB[aa+8] = H.y; iB[aa+8] = H.w;
    }
    fft16_nat<1>(rA, iA);
    fft16_nat<1>(rB, iB);
    twiddle_stage<1, 1>(rA, iA, (float)u * D256);
    twiddle_stage<1, 1>(rB, iB, (float)(u + 8) * D256);
    __syncthreads();
    #pragma unroll
    for (int c2 = 0; c2 < 16; ++c2){
        const int s = REV(c2);
        sb[(16 * c2 + c1) * S2R + u] = make_float4(rA[s], rB[s], iA[s], iB[s]);
    }
    __syncthreads();
    // stage 3 inv: lanes = (m = t, t+128); rename
    #pragma unroll
    for (int uu = 0; uu < 8; ++uu){
        const float4 L = sb[t * S2R + uu];
        const float4 H = sb[(t + 128) * S2R + uu];
        rA[uu]   = L.x; iA[uu]   = L.z; rB[uu]   = H.x; iB[uu]   = H.z;
        rA[uu+8] = L.y; iA[uu+8] = L.w; rB[uu+8] = H.y; iB[uu+8] = H.w;
    }
    fft16_nat<1>(rA, iA);
    fft16_nat<1>(rB, iB);        // out[256*d2 + m] at slot REV(d2)

    // ---- store ----
    #pragma unroll
    for (int d2 = 0; d2 < 16; ++d2){
        const int s = REV(d2);
        out2[rb2 + 256 * d2 + t]       = make_float2(rA[s], iA[s]);
        out2[rb2 + 256 * d2 + t + 128] = make_float2(rB[s], iB[s]);
    }
}

extern "C" void kernel_launch(void* const* d_in, const int* in_sizes, int n_in,
                              void* d_out, int out_size)
{
    const float4* x4 = (const float4*)d_in[0];
    const float4* A4 = (const float4*)d_in[1];
    const float2* D2 = (const float2*)d_in[2];
    float2* out2 = (float2*)d_out;

    const int rows = in_sizes[0] / (4096 * 2);
    afdf_fft6_kernel<<<rows, 128>>>(x4, A4, D2, out2);
}

// round 7
// speedup vs baseline: 1.0432x; 1.0432x over previous
#include <cuda_runtime.h>
#include <cuda_fp16.h>
#include <cstdint>

// out = IFFT( D .* FFT( A .* x ) ) per row, C = 4096, complex as (re,im) float pairs.
// A, D scale re/im independently (elementwise).
//
// 128 threads per row; each thread carries TWO lanes as scalar floats.
// 4096 = 16^3: three radix-16 register stages; two shared exchanges per
// direction with entries stored as fp16: {half2(reA,imA), half2(reB,imB)} = 8B.
// Halves LDS/STS bytes vs fp32. Strides 129 / 9 -> conflict-free 64-bit access.
// Separate s1/s2 buffers -> only 4 __syncthreads total.

#define REV(c) ((((c) & 3) << 2) | ((c) >> 2))

struct __align__(8) E { __half2 a, b; };

__device__ __forceinline__ E epack(float rA, float iA, float rB, float iB){
    E e; e.a = __floats2half2_rn(rA, iA); e.b = __floats2half2_rn(rB, iB); return e;
}

// complex multiply, 4 instrs
__device__ __forceinline__ void cmul(float& r, float& i, float wr, float wi){
    float t = i * wi;
    float u = i * wr;
    float nr = fmaf(r, wr, -t);
    i = fmaf(r, wi, u);
    r = nr;
}
template<int DIR> __device__ __forceinline__ void mulj(float& r, float& i){
    float t = r;
    if (DIR < 0){ r = i;  i = -t; }
    else        { r = -i; i = t;  }
}
template<int DIR> __device__ __forceinline__ void cmulc(float& r, float& i, float cr, float ci_f){
    cmul(r, i, cr, (DIR < 0) ? ci_f : -ci_f);
}

#define TC1 0.92387953251128674f
#define TS1 0.38268343236508978f
#define TC2 0.70710678118654752f

template<int DIR>
__device__ __forceinline__ void fft4s(float& r0, float& i0, float& r1, float& i1,
                                      float& r2, float& i2, float& r3, float& i3){
    float t0r = r0 + r2, t0i = i0 + i2;
    float t1r = r0 - r2, t1i = i0 - i2;
    float t2r = r1 + r3, t2i = i1 + i3;
    float t3r, t3i;
    if (DIR < 0){ t3r = i1 - i3; t3i = r3 - r1; }
    else        { t3r = i3 - i1; t3i = r1 - r3; }
    r0 = t0r + t2r; i0 = t0i + t2i;
    r2 = t0r - t2r; i2 = t0i - t2i;
    r1 = t1r + t3r; i1 = t1i + t3i;
    r3 = t1r - t3r; i3 = t1i - t3i;
}

template<int DIR>
__device__ __forceinline__ void fft16_nat(float r[16], float i[16]){
    fft4s<DIR>(r[0],i[0], r[4],i[4], r[8], i[8],  r[12],i[12]);
    fft4s<DIR>(r[1],i[1], r[5],i[5], r[9], i[9],  r[13],i[13]);
    fft4s<DIR>(r[2],i[2], r[6],i[6], r[10],i[10], r[14],i[14]);
    fft4s<DIR>(r[3],i[3], r[7],i[7], r[11],i[11], r[15],i[15]);
    cmulc<DIR>(r[5], i[5],  TC1, -TS1);
    cmulc<DIR>(r[9], i[9],  TC2, -TC2);
    cmulc<DIR>(r[13],i[13], TS1, -TC1);
    cmulc<DIR>(r[6], i[6],  TC2, -TC2);
    mulj<DIR>(r[10],i[10]);
    cmulc<DIR>(r[14],i[14],-TC2, -TC2);
    cmulc<DIR>(r[7], i[7],  TS1, -TC1);
    cmulc<DIR>(r[11],i[11],-TC2, -TC2);
    cmulc<DIR>(r[15],i[15],-TC1,  TS1);
    fft4s<DIR>(r[0], i[0],  r[1], i[1],  r[2], i[2],  r[3], i[3]);
    fft4s<DIR>(r[4], i[4],  r[5], i[5],  r[6], i[6],  r[7], i[7]);
    fft4s<DIR>(r[8], i[8],  r[9], i[9],  r[10],i[10], r[11],i[11]);
    fft4s<DIR>(r[12],i[12], r[13],i[13], r[14],i[14], r[15],i[15]);
}

template<int DIR>
__device__ __forceinline__ void fft16_rev(float r[16], float i[16]){
    fft4s<DIR>(r[0], i[0],  r[1], i[1],  r[2], i[2],  r[3], i[3]);
    fft4s<DIR>(r[4], i[4],  r[5], i[5],  r[6], i[6],  r[7], i[7]);
    fft4s<DIR>(r[8], i[8],  r[9], i[9],  r[10],i[10], r[11],i[11]);
    fft4s<DIR>(r[12],i[12], r[13],i[13], r[14],i[14], r[15],i[15]);
    cmulc<DIR>(r[5], i[5],  TC1, -TS1);
    cmulc<DIR>(r[6], i[6],  TC2, -TC2);
    cmulc<DIR>(r[7], i[7],  TS1, -TC1);
    cmulc<DIR>(r[9], i[9],  TC2, -TC2);
    mulj<DIR>(r[10],i[10]);
    cmulc<DIR>(r[11],i[11],-TC2, -TC2);
    cmulc<DIR>(r[13],i[13], TS1, -TC1);
    cmulc<DIR>(r[14],i[14],-TC2, -TC2);
    cmulc<DIR>(r[15],i[15],-TC1,  TS1);
    fft4s<DIR>(r[0],i[0], r[4],i[4], r[8], i[8],  r[12],i[12]);
    fft4s<DIR>(r[1],i[1], r[5],i[5], r[9], i[9],  r[13],i[13]);
    fft4s<DIR>(r[2],i[2], r[6],i[6], r[10],i[10], r[14],i[14]);
    fft4s<DIR>(r[3],i[3], r[7],i[7], r[11],i[11], r[15],i[15]);
}

template<int DIR, int RV>
__device__ __forceinline__ void twiddle_stage(float r[16], float i[16], float theta){
    float sn, cs;
    __sincosf(theta, &sn, &cs);
    if (DIR < 0) sn = -sn;
    float w2r = fmaf(cs, cs, -(sn * sn));
    float w2i = 2.0f * cs * sn;
    float por = cs,  poi = sn;
    float per = w2r, pei = w2i;
    #pragma unroll
    for (int k = 1; k < 16; ++k){
        const int slot = RV ? REV(k) : k;
        if (k & 1){
            cmul(r[slot], i[slot], por, poi);
            if (k + 2 < 16) cmul(por, poi, w2r, w2i);
        } else {
            cmul(r[slot], i[slot], per, pei);
            if (k + 2 < 16) cmul(per, pei, w2r, w2i);
        }
    }
}

#define S1R 129   // entry stride (8B units), odd -> conflict-free 64-bit access
#define S2R 9
#define D4096 1.5339807878856412e-3f   // 2*pi/4096
#define D256  2.4543692606170259e-2f   // 2*pi/256
#define INV_N (1.0f / 4096.0f)

__global__ void __launch_bounds__(128, 4) afdf_fft7_kernel(
    const float4* __restrict__ x4,
    const float4* __restrict__ A4,
    const float2* __restrict__ D2,
    float2* __restrict__ out2)
{
    __shared__ E s1[16 * S1R];    // 2064 * 8B = 16.5 KB
    __shared__ E s2[256 * S2R];   // 2304 * 8B = 18.4 KB

    const int t  = threadIdx.x;        // 0..127
    const int c1 = t & 15;
    const int u  = t >> 4;             // 0..7
    const size_t rb4 = (size_t)blockIdx.x * 2048;
    const size_t rb2 = (size_t)blockIdx.x * 4096;

    float rA[16], iA[16], rB[16], iB[16];

    // ---- load x, apply A; lanes = points m = (2t, 2t+1) ----
    #pragma unroll
    for (int a = 0; a < 16; ++a){
        const float4 xv = x4[rb4 + 128 * a + t];
        const float4 av = A4[128 * a + t];
        rA[a] = xv.x * av.x;  iA[a] = xv.y * av.y;
        rB[a] = xv.z * av.z;  iB[a] = xv.w * av.w;
    }

    // ================= forward =================
    fft16_nat<-1>(rA, iA);
    fft16_nat<-1>(rB, iB);
    twiddle_stage<-1, 1>(rA, iA, (float)(2*t)     * D4096);
    twiddle_stage<-1, 1>(rB, iB, (float)(2*t + 1) * D4096);
    #pragma unroll
    for (int c = 0; c < 16; ++c){
        const int s = REV(c);
        s1[c * S1R + t] = epack(rA[s], iA[s], rB[s], iB[s]);
    }
    __syncthreads();                         // (1)
    // stage 2: lanes = (b2 = 2u, 2u+1)
    #pragma unroll
    for (int a2 = 0; a2 < 16; ++a2){
        const E e = s1[c1 * S1R + 8 * a2 + u];
        const float2 fa = __half22float2(e.a);
        const float2 fb = __half22float2(e.b);
        rA[a2] = fa.x; iA[a2] = fa.y; rB[a2] = fb.x; iB[a2] = fb.y;
    }
    fft16_nat<-1>(rA, iA);
    fft16_nat<-1>(rB, iB);
    twiddle_stage<-1, 1>(rA, iA, (float)(2*u)     * D256);
    twiddle_stage<-1, 1>(rB, iB, (float)(2*u + 1) * D256);
    #pragma unroll
    for (int c2 = 0; c2 < 16; ++c2){
        const int s = REV(c2);
        s2[(16 * c2 + c1) * S2R + u] = epack(rA[s], iA[s], rB[s], iB[s]);
    }
    __syncthreads();                         // (2)
    // stage 3: lanes = (r = t, t+128); stored pairs along b2 -> rename
    #pragma unroll
    for (int uu = 0; uu < 8; ++uu){
        const E L = s2[t * S2R + uu];
        const E H = s2[(t + 128) * S2R + uu];
        const float2 La = __half22float2(L.a), Lb = __half22float2(L.b);
        const float2 Ha = __half22float2(H.a), Hb = __half22float2(H.b);
        rA[2*uu]   = La.x; iA[2*uu]   = La.y; rB[2*uu]   = Ha.x; iB[2*uu]   = Ha.y;
        rA[2*uu+1] = Lb.x; iA[2*uu+1] = Lb.y; rB[2*uu+1] = Hb.x; iB[2*uu+1] = Hb.y;
    }
    fft16_nat<-1>(rA, iA);
    fft16_nat<-1>(rB, iB);      // F[256*d2 + r] at slot REV(d2)

    // ---- D scale (1/N folded), freq = 256*d2 + (t | t+128) ----
    #pragma unroll
    for (int d2 = 0; d2 < 16; ++d2){
        const float2 da = D2[256 * d2 + t];
        const float2 db = D2[256 * d2 + t + 128];
        const int s = REV(d2);
        rA[s] *= da.x * INV_N;  iA[s] *= da.y * INV_N;
        rB[s] *= db.x * INV_N;  iB[s] *= db.y * INV_N;
    }

    // ================= inverse =================
    fft16_rev<1>(rA, iA);
    fft16_rev<1>(rB, iB);
    twiddle_stage<1, 0>(rA, iA, (float)t * D4096);
    twiddle_stage<1, 0>(rB, iB, (float)(t + 128) * D4096);
    // s1 reuse: forward-ex1 reads happened-before barrier (2) -> safe to store
    #pragma unroll
    for (int c = 0; c < 16; ++c){
        s1[c * S1R + t] = epack(rA[c], iA[c], rB[c], iB[c]);  // lanes (r=t, t+128)
    }
    __syncthreads();                         // (3)
    // stage 2 inv: lanes = (b2 = u, u+8)
    #pragma unroll
    for (int aa = 0; aa < 8; ++aa){
        const E L = s1[c1 * S1R + 16 * aa + u];
        const E H = s1[c1 * S1R + 16 * aa + u + 8];
        const float2 La = __half22float2(L.a), Lb = __half22float2(L.b);
        const float2 Ha = __half22float2(H.a), Hb = __half22float2(H.b);
        rA[aa]   = La.x; iA[aa]   = La.y; rB[aa]   = Ha.x; iB[aa]   = Ha.y;
        rA[aa+8] = Lb.x; iA[aa+8] = Lb.y; rB[aa+8] = Hb.x; iB[aa+8] = Hb.y;
    }
    fft16_nat<1>(rA, iA);
    fft16_nat<1>(rB, iB);
    twiddle_stage<1, 1>(rA, iA, (float)u * D256);
    twiddle_stage<1, 1>(rB, iB, (float)(u + 8) * D256);
    // s2 reuse: forward stage-3 reads happened-before barrier (3) -> safe
    #pragma unroll
    for (int c2 = 0; c2 < 16; ++c2){
        const int s = REV(c2);
        s2[(16 * c2 + c1) * S2R + u] = epack(rA[s], iA[s], rB[s], iB[s]);
    }
    __syncthreads();                         // (4)
    // stage 3 inv: lanes = (m = t, t+128)
    #pragma unroll
    for (int uu = 0; uu < 8; ++uu){
        const E L = s2[t * S2R + uu];
        const E H = s2[(t + 128) * S2R + uu];
        const float2 La = __half22float2(L.a), Lb = __half22float2(L.b);
        const float2 Ha = __half22float2(H.a), Hb = __half22float2(H.b);
        rA[uu]   = La.x; iA[uu]   = La.y; rB[uu]   = Ha.x; iB[uu]   = Ha.y;
        rA[uu+8] = Lb.x; iA[uu+8] = Lb.y; rB[uu+8] = Hb.x; iB[uu+8] = Hb.y;
    }
    fft16_nat<1>(rA, iA);
    fft16_nat<1>(rB, iB);        // out[256*d2 + m] at slot REV(d2)

    // ---- store ----
    #pragma unroll
    for (int d2 = 0; d2 < 16; ++d2){
        const int s = REV(d2);
        out2[rb2 + 256 * d2 + t]       = make_float2(rA[s], iA[s]);
        out2[rb2 + 256 * d2 + t + 128] = make_float2(rB[s], iB[s]);
    }
}

extern "C" void kernel_launch(void* const* d_in, const int* in_sizes, int n_in,
                              void* d_out, int out_size)
{
    const float4* x4 = (const float4*)d_in[0];
    const float4* A4 = (const float4*)d_in[1];
    const float2* D2 = (const float2*)d_in[2];
    float2* out2 = (float2*)d_out;

    const int rows = in_sizes[0] / (4096 * 2);
    afdf_fft7_kernel<<<rows, 128>>>(x4, A4, D2, out2);
}

// round 8
// speedup vs baseline: 1.0883x; 1.0432x over previous
#include <cuda_runtime.h>
#include <cstdint>

// out = IFFT( D .* FFT( A .* x ) ) per row, C = 4096, complex as (re,im) float pairs.
// A, D scale re/im independently (elementwise).
//
// 256 threads per row, ONE lane per thread (16 points) -> ~64 regs -> high occupancy.
// 4096 = 16^3: three radix-16 register stages; two shared exchanges per direction
// as float2 {re,im} entries (8B LDS/STS), strides 257 / 17 -> conflict-free per
// 16-lane phase. Twiddles via one __sincosf + odd/even power chains per stage.

#define REV(c) ((((c) & 3) << 2) | ((c) >> 2))

__device__ __forceinline__ void cmul(float& r, float& i, float wr, float wi){
    float t = i * wi;
    float u = i * wr;
    float nr = fmaf(r, wr, -t);
    i = fmaf(r, wi, u);
    r = nr;
}
template<int DIR> __device__ __forceinline__ void mulj(float& r, float& i){
    float t = r;
    if (DIR < 0){ r = i;  i = -t; }
    else        { r = -i; i = t;  }
}
template<int DIR> __device__ __forceinline__ void cmulc(float& r, float& i, float cr, float ci_f){
    cmul(r, i, cr, (DIR < 0) ? ci_f : -ci_f);
}

#define TC1 0.92387953251128674f
#define TS1 0.38268343236508978f
#define TC2 0.70710678118654752f

template<int DIR>
__device__ __forceinline__ void fft4s(float& r0, float& i0, float& r1, float& i1,
                                      float& r2, float& i2, float& r3, float& i3){
    float t0r = r0 + r2, t0i = i0 + i2;
    float t1r = r0 - r2, t1i = i0 - i2;
    float t2r = r1 + r3, t2i = i1 + i3;
    float t3r, t3i;
    if (DIR < 0){ t3r = i1 - i3; t3i = r3 - r1; }
    else        { t3r = i3 - i1; t3i = r1 - r3; }
    r0 = t0r + t2r; i0 = t0i + t2i;
    r2 = t0r - t2r; i2 = t0i - t2i;
    r1 = t1r + t3r; i1 = t1i + t3i;
    r3 = t1r - t3r; i3 = t1i - t3i;
}

// 16-point DFT, natural slots in -> output c at slot REV(c)
template<int DIR>
__device__ __forceinline__ void fft16_nat(float r[16], float i[16]){
    fft4s<DIR>(r[0],i[0], r[4],i[4], r[8], i[8],  r[12],i[12]);
    fft4s<DIR>(r[1],i[1], r[5],i[5], r[9], i[9],  r[13],i[13]);
    fft4s<DIR>(r[2],i[2], r[6],i[6], r[10],i[10], r[14],i[14]);
    fft4s<DIR>(r[3],i[3], r[7],i[7], r[11],i[11], r[15],i[15]);
    cmulc<DIR>(r[5], i[5],  TC1, -TS1);
    cmulc<DIR>(r[9], i[9],  TC2, -TC2);
    cmulc<DIR>(r[13],i[13], TS1, -TC1);
    cmulc<DIR>(r[6], i[6],  TC2, -TC2);
    mulj<DIR>(r[10],i[10]);
    cmulc<DIR>(r[14],i[14],-TC2, -TC2);
    cmulc<DIR>(r[7], i[7],  TS1, -TC1);
    cmulc<DIR>(r[11],i[11],-TC2, -TC2);
    cmulc<DIR>(r[15],i[15],-TC1,  TS1);
    fft4s<DIR>(r[0], i[0],  r[1], i[1],  r[2], i[2],  r[3], i[3]);
    fft4s<DIR>(r[4], i[4],  r[5], i[5],  r[6], i[6],  r[7], i[7]);
    fft4s<DIR>(r[8], i[8],  r[9], i[9],  r[10],i[10], r[11],i[11]);
    fft4s<DIR>(r[12],i[12], r[13],i[13], r[14],i[14], r[15],i[15]);
}

// 16-point DFT, input logical a at slot REV(a) -> natural output slots
template<int DIR>
__device__ __forceinline__ void fft16_rev(float r[16], float i[16]){
    fft4s<DIR>(r[0], i[0],  r[1], i[1],  r[2], i[2],  r[3], i[3]);
    fft4s<DIR>(r[4], i[4],  r[5], i[5],  r[6], i[6],  r[7], i[7]);
    fft4s<DIR>(r[8], i[8],  r[9], i[9],  r[10],i[10], r[11],i[11]);
    fft4s<DIR>(r[12],i[12], r[13],i[13], r[14],i[14], r[15],i[15]);
    cmulc<DIR>(r[5], i[5],  TC1, -TS1);
    cmulc<DIR>(r[6], i[6],  TC2, -TC2);
    cmulc<DIR>(r[7], i[7],  TS1, -TC1);
    cmulc<DIR>(r[9], i[9],  TC2, -TC2);
    mulj<DIR>(r[10],i[10]);
    cmulc<DIR>(r[11],i[11],-TC2, -TC2);
    cmulc<DIR>(r[13],i[13], TS1, -TC1);
    cmulc<DIR>(r[14],i[14],-TC2, -TC2);
    cmulc<DIR>(r[15],i[15],-TC1,  TS1);
    fft4s<DIR>(r[0],i[0], r[4],i[4], r[8], i[8],  r[12],i[12]);
    fft4s<DIR>(r[1],i[1], r[5],i[5], r[9], i[9],  r[13],i[13]);
    fft4s<DIR>(r[2],i[2], r[6],i[6], r[10],i[10], r[14],i[14]);
    fft4s<DIR>(r[3],i[3], r[7],i[7], r[11],i[11], r[15],i[15]);
}

// apply w^k to v[slot(k)], k=1..15; w = e^{DIR*i*theta}
template<int DIR, int RV>
__device__ __forceinline__ void twiddle_stage(float r[16], float i[16], float theta){
    float sn, cs;
    __sincosf(theta, &sn, &cs);
    if (DIR < 0) sn = -sn;
    float w2r = fmaf(cs, cs, -(sn * sn));
    float w2i = 2.0f * cs * sn;
    float por = cs,  poi = sn;
    float per = w2r, pei = w2i;
    #pragma unroll
    for (int k = 1; k < 16; ++k){
        const int slot = RV ? REV(k) : k;
        if (k & 1){
            cmul(r[slot], i[slot], por, poi);
            if (k + 2 < 16) cmul(por, poi, w2r, w2i);
        } else {
            cmul(r[slot], i[slot], per, pei);
            if (k + 2 < 16) cmul(per, pei, w2r, w2i);
        }
    }
}

#define S1R 257   // float2-entry stride; 257 mod 16 = 1 -> conflict-free 8B access
#define S2R 17    // 17 mod 16 = 1 -> conflict-free
#define D4096 1.5339807878856412e-3f   // 2*pi/4096
#define D256  2.4543692606170259e-2f   // 2*pi/256
#define INV_N (1.0f / 4096.0f)

__global__ void __launch_bounds__(256, 4) afdf_fft8_kernel(
    const float2* __restrict__ x2,
    const float2* __restrict__ A2,
    const float2* __restrict__ D2,
    float2* __restrict__ out2)
{
    // aliased views: S1 = 16 rows x 257 entries (4112); S2 = 256 rows x 17 (4352)
    __shared__ float2 sb[256 * S2R];   // 4352 * 8B = 34,816 B

    const int t    = threadIdx.x;      // 0..255
    const int c_lo = t & 15;
    const int b2   = t >> 4;           // 0..15
    const size_t base = (size_t)blockIdx.x * 4096;

    float r[16], i[16];

    // ---- load + A scale (elementwise re/im), points m = t + 256*a ----
    #pragma unroll
    for (int a = 0; a < 16; ++a){
        const int n = t + 256 * a;
        const float2 xv = x2[base + n];
        const float2 av = A2[n];
        r[a] = xv.x * av.x;
        i[a] = xv.y * av.y;
    }

    // ================= forward =================
    fft16_nat<-1>(r, i);                                 // U[c] at REV(c)
    twiddle_stage<-1, 1>(r, i, (float)t * D4096);        // * w4096^{t c}
    #pragma unroll
    for (int c = 0; c < 16; ++c){
        const int s = REV(c);
        sb[c * S1R + t] = make_float2(r[s], i[s]);
    }
    __syncthreads();
    #pragma unroll
    for (int a2 = 0; a2 < 16; ++a2){
        const float2 v = sb[c_lo * S1R + 16 * a2 + b2];
        r[a2] = v.x; i[a2] = v.y;
    }
    fft16_nat<-1>(r, i);
    twiddle_stage<-1, 1>(r, i, (float)b2 * D256);        // * w256^{b2 c2}
    __syncthreads();                                     // alias: ex1 reads done
    #pragma unroll
    for (int c2 = 0; c2 < 16; ++c2){
        const int s = REV(c2);
        sb[(c2 * 16 + c_lo) * S2R + b2] = make_float2(r[s], i[s]);
    }
    __syncthreads();
    #pragma unroll
    for (int b = 0; b < 16; ++b){
        const float2 v = sb[t * S2R + b];
        r[b] = v.x; i[b] = v.y;
    }
    fft16_nat<-1>(r, i);
    // now F[256*d2 + t] sits at slot REV(d2)

    // ---- D scale (1/N folded) ----
    #pragma unroll
    for (int d2 = 0; d2 < 16; ++d2){
        const float2 dv = D2[t + 256 * d2];
        const int s = REV(d2);
        r[s] *= dv.x * INV_N;
        i[s] *= dv.y * INV_N;
    }
    __syncthreads();   // protect aliased buffer across directions

    // ================= inverse =================
    fft16_rev<1>(r, i);                                  // REV in -> natural out
    twiddle_stage<1, 0>(r, i, (float)t * D4096);
    #pragma unroll
    for (int c = 0; c < 16; ++c){
        sb[c * S1R + t] = make_float2(r[c], i[c]);
    }
    __syncthreads();
    #pragma unroll
    for (int a2 = 0; a2 < 16; ++a2){
        const float2 v = sb[c_lo * S1R + 16 * a2 + b2];
        r[a2] = v.x; i[a2] = v.y;
    }
    fft16_nat<1>(r, i);
    twiddle_stage<1, 1>(r, i, (float)b2 * D256);
    __syncthreads();
    #pragma unroll
    for (int c2 = 0; c2 < 16; ++c2){
        const int s = REV(c2);
        sb[(c2 * 16 + c_lo) * S2R + b2] = make_float2(r[s], i[s]);
    }
    __syncthreads();
    #pragma unroll
    for (int b = 0; b < 16; ++b){
        const float2 v = sb[t * S2R + b];
        r[b] = v.x; i[b] = v.y;
    }
    fft16_nat<1>(r, i);
    // out[256*d2 + t] at slot REV(d2)

    // ---- store ----
    #pragma unroll
    for (int d2 = 0; d2 < 16; ++d2){
        const int s = REV(d2);
        out2[base + t + 256 * d2] = make_float2(r[s], i[s]);
    }
}

extern "C" void kernel_launch(void* const* d_in, const int* in_sizes, int n_in,
                              void* d_out, int out_size)
{
    const float2* x2 = (const float2*)d_in[0];
    const float2* A2 = (const float2*)d_in[1];
    const float2* D2 = (const float2*)d_in[2];
    float2* out2 = (float2*)d_out;

    const int rows = in_sizes[0] / (4096 * 2);
    afdf_fft8_kernel<<<rows, 256>>>(x2, A2, D2, out2);
}

// round 9
// speedup vs baseline: 1.0899x; 1.0014x over previous
#include <cuda_runtime.h>
#include <cuda_fp16.h>
#include <cstdint>

// out = IFFT( D .* FFT( A .* x ) ) per row, C = 4096, complex as (re,im) float pairs.
// A, D scale re/im independently (elementwise).
//
// 256 threads per row, ONE lane per thread (16 points) -> 64 regs -> 48% occupancy.
// 4096 = 16^3: three radix-16 register stages; two shared exchanges per direction
// staged in fp16 (__half2{re,im} = 4B entries, half the L1 bytes of fp32):
//   s1: stride 258 (== 2 mod 32)  -> ex1 write & stage-2 read conflict-free
//   s2: stride 18; stage-3 reads as 8B uint2 pairs -> conflict-free
// Separate s1/s2 buffers -> only 4 __syncthreads. Twiddles via one __sincosf +
// odd/even power chains per stage (fp32 math throughout; fp16 only in smem).

#define REV(c) ((((c) & 3) << 2) | ((c) >> 2))

__device__ __forceinline__ void cmul(float& r, float& i, float wr, float wi){
    float t = i * wi;
    float u = i * wr;
    float nr = fmaf(r, wr, -t);
    i = fmaf(r, wi, u);
    r = nr;
}
template<int DIR> __device__ __forceinline__ void mulj(float& r, float& i){
    float t = r;
    if (DIR < 0){ r = i;  i = -t; }
    else        { r = -i; i = t;  }
}
template<int DIR> __device__ __forceinline__ void cmulc(float& r, float& i, float cr, float ci_f){
    cmul(r, i, cr, (DIR < 0) ? ci_f : -ci_f);
}

#define TC1 0.92387953251128674f
#define TS1 0.38268343236508978f
#define TC2 0.70710678118654752f

template<int DIR>
__device__ __forceinline__ void fft4s(float& r0, float& i0, float& r1, float& i1,
                                      float& r2, float& i2, float& r3, float& i3){
    float t0r = r0 + r2, t0i = i0 + i2;
    float t1r = r0 - r2, t1i = i0 - i2;
    float t2r = r1 + r3, t2i = i1 + i3;
    float t3r, t3i;
    if (DIR < 0){ t3r = i1 - i3; t3i = r3 - r1; }
    else        { t3r = i3 - i1; t3i = r1 - r3; }
    r0 = t0r + t2r; i0 = t0i + t2i;
    r2 = t0r - t2r; i2 = t0i - t2i;
    r1 = t1r + t3r; i1 = t1i + t3i;
    r3 = t1r - t3r; i3 = t1i - t3i;
}

// 16-point DFT, natural slots in -> output c at slot REV(c)
template<int DIR>
__device__ __forceinline__ void fft16_nat(float r[16], float i[16]){
    fft4s<DIR>(r[0],i[0], r[4],i[4], r[8], i[8],  r[12],i[12]);
    fft4s<DIR>(r[1],i[1], r[5],i[5], r[9], i[9],  r[13],i[13]);
    fft4s<DIR>(r[2],i[2], r[6],i[6], r[10],i[10], r[14],i[14]);
    fft4s<DIR>(r[3],i[3], r[7],i[7], r[11],i[11], r[15],i[15]);
    cmulc<DIR>(r[5], i[5],  TC1, -TS1);
    cmulc<DIR>(r[9], i[9],  TC2, -TC2);
    cmulc<DIR>(r[13],i[13], TS1, -TC1);
    cmulc<DIR>(r[6], i[6],  TC2, -TC2);
    mulj<DIR>(r[10],i[10]);
    cmulc<DIR>(r[14],i[14],-TC2, -TC2);
    cmulc<DIR>(r[7], i[7],  TS1, -TC1);
    cmulc<DIR>(r[11],i[11],-TC2, -TC2);
    cmulc<DIR>(r[15],i[15],-TC1,  TS1);
    fft4s<DIR>(r[0], i[0],  r[1], i[1],  r[2], i[2],  r[3], i[3]);
    fft4s<DIR>(r[4], i[4],  r[5], i[5],  r[6], i[6],  r[7], i[7]);
    fft4s<DIR>(r[8], i[8],  r[9], i[9],  r[10],i[10], r[11],i[11]);
    fft4s<DIR>(r[12],i[12], r[13],i[13], r[14],i[14], r[15],i[15]);
}

// 16-point DFT, input logical a at slot REV(a) -> natural output slots
template<int DIR>
__device__ __forceinline__ void fft16_rev(float r[16], float i[16]){
    fft4s<DIR>(r[0], i[0],  r[1], i[1],  r[2], i[2],  r[3], i[3]);
    fft4s<DIR>(r[4], i[4],  r[5], i[5],  r[6], i[6],  r[7], i[7]);
    fft4s<DIR>(r[8], i[8],  r[9], i[9],  r[10],i[10], r[11],i[11]);
    fft4s<DIR>(r[12],i[12], r[13],i[13], r[14],i[14], r[15],i[15]);
    cmulc<DIR>(r[5], i[5],  TC1, -TS1);
    cmulc<DIR>(r[6], i[6],  TC2, -TC2);
    cmulc<DIR>(r[7], i[7],  TS1, -TC1);
    cmulc<DIR>(r[9], i[9],  TC2, -TC2);
    mulj<DIR>(r[10],i[10]);
    cmulc<DIR>(r[11],i[11],-TC2, -TC2);
    cmulc<DIR>(r[13],i[13], TS1, -TC1);
    cmulc<DIR>(r[14],i[14],-TC2, -TC2);
    cmulc<DIR>(r[15],i[15],-TC1,  TS1);
    fft4s<DIR>(r[0],i[0], r[4],i[4], r[8], i[8],  r[12],i[12]);
    fft4s<DIR>(r[1],i[1], r[5],i[5], r[9], i[9],  r[13],i[13]);
    fft4s<DIR>(r[2],i[2], r[6],i[6], r[10],i[10], r[14],i[14]);
    fft4s<DIR>(r[3],i[3], r[7],i[7], r[11],i[11], r[15],i[15]);
}

// apply w^k to v[slot(k)], k=1..15; w = e^{DIR*i*theta}
template<int DIR, int RV>
__device__ __forceinline__ void twiddle_stage(float r[16], float i[16], float theta){
    float sn, cs;
    __sincosf(theta, &sn, &cs);
    if (DIR < 0) sn = -sn;
    float w2r = fmaf(cs, cs, -(sn * sn));
    float w2i = 2.0f * cs * sn;
    float por = cs,  poi = sn;
    float per = w2r, pei = w2i;
    #pragma unroll
    for (int k = 1; k < 16; ++k){
        const int slot = RV ? REV(k) : k;
        if (k & 1){
            cmul(r[slot], i[slot], por, poi);
            if (k + 2 < 16) cmul(por, poi, w2r, w2i);
        } else {
            cmul(r[slot], i[slot], per, pei);
            if (k + 2 < 16) cmul(per, pei, w2r, w2i);
        }
    }
}

#define S1H 258   // half2-entry stride; 258 mod 32 = 2 -> ex1 patterns conflict-free
#define S2H 18    // half2-entry stride; even (8B-aligned rows), conflict-free W2/R3
#define D4096 1.5339807878856412e-3f   // 2*pi/4096
#define D256  2.4543692606170259e-2f   // 2*pi/256
#define INV_N (1.0f / 4096.0f)

__global__ void __launch_bounds__(256, 4) afdf_fft9_kernel(
    const float2* __restrict__ x2,
    const float2* __restrict__ A2,
    const float2* __restrict__ D2,
    float2* __restrict__ out2)
{
    __shared__ __align__(16) __half2 s1h[16 * S1H];    // 16,512 B
    __shared__ __align__(16) __half2 s2h[256 * S2H];   // 18,432 B

    const int t    = threadIdx.x;      // 0..255
    const int c_lo = t & 15;
    const int b2   = t >> 4;           // 0..15
    const size_t base = (size_t)blockIdx.x * 4096;

    float r[16], i[16];

    // ---- load + A scale (elementwise re/im), points m = t + 256*a ----
    #pragma unroll
    for (int a = 0; a < 16; ++a){
        const int n = t + 256 * a;
        const float2 xv = x2[base + n];
        const float2 av = A2[n];
        r[a] = xv.x * av.x;
        i[a] = xv.y * av.y;
    }

    // ================= forward =================
    fft16_nat<-1>(r, i);                                 // U[c] at REV(c)
    twiddle_stage<-1, 1>(r, i, (float)t * D4096);        // * w4096^{t c}
    #pragma unroll
    for (int c = 0; c < 16; ++c){
        const int s = REV(c);
        s1h[c * S1H + t] = __floats2half2_rn(r[s], i[s]);
    }
    __syncthreads();                                     // (1)
    #pragma unroll
    for (int a2 = 0; a2 < 16; ++a2){
        const float2 v = __half22float2(s1h[c_lo * S1H + 16 * a2 + b2]);
        r[a2] = v.x; i[a2] = v.y;
    }
    fft16_nat<-1>(r, i);
    twiddle_stage<-1, 1>(r, i, (float)b2 * D256);        // * w256^{b2 c2}
    #pragma unroll
    for (int c2 = 0; c2 < 16; ++c2){
        const int s = REV(c2);
        s2h[(c2 * 16 + c_lo) * S2H + b2] = __floats2half2_rn(r[s], i[s]);
    }
    __syncthreads();                                     // (2)
    #pragma unroll
    for (int j = 0; j < 8; ++j){
        const uint2 u = *reinterpret_cast<const uint2*>(s2h + t * S2H + 2 * j);
        const float2 v0 = __half22float2(*reinterpret_cast<const __half2*>(&u.x));
        const float2 v1 = __half22float2(*reinterpret_cast<const __half2*>(&u.y));
        r[2*j]   = v0.x; i[2*j]   = v0.y;
        r[2*j+1] = v1.x; i[2*j+1] = v1.y;
    }
    fft16_nat<-1>(r, i);
    // now F[256*d2 + t] sits at slot REV(d2)

    // ---- D scale (1/N folded) ----
    #pragma unroll
    for (int d2 = 0; d2 < 16; ++d2){
        const float2 dv = D2[t + 256 * d2];
        const int s = REV(d2);
        r[s] *= dv.x * INV_N;
        i[s] *= dv.y * INV_N;
    }

    // ================= inverse =================
    fft16_rev<1>(r, i);                                  // REV in -> natural out
    twiddle_stage<1, 0>(r, i, (float)t * D4096);
    // s1 reuse: all ex1 reads happened-before barrier (2)
    #pragma unroll
    for (int c = 0; c < 16; ++c){
        s1h[c * S1H + t] = __floats2half2_rn(r[c], i[c]);
    }
    __syncthreads();                                     // (3)
    #pragma unroll
    for (int a2 = 0; a2 < 16; ++a2){
        const float2 v = __half22float2(s1h[c_lo * S1H + 16 * a2 + b2]);
        r[a2] = v.x; i[a2] = v.y;
    }
    fft16_nat<1>(r, i);
    twiddle_stage<1, 1>(r, i, (float)b2 * D256);
    // s2 reuse: stage-3 fwd reads happened-before barrier (3)
    #pragma unroll
    for (int c2 = 0; c2 < 16; ++c2){
        const int s = REV(c2);
        s2h[(c2 * 16 + c_lo) * S2H + b2] = __floats2half2_rn(r[s], i[s]);
    }
    __syncthreads();                                     // (4)
    #pragma unroll
    for (int j = 0; j < 8; ++j){
        const uint2 u = *reinterpret_cast<const uint2*>(s2h + t * S2H + 2 * j);
        const float2 v0 = __half22float2(*reinterpret_cast<const __half2*>(&u.x));
        const float2 v1 = __half22float2(*reinterpret_cast<const __half2*>(&u.y));
        r[2*j]   = v0.x; i[2*j]   = v0.y;
        r[2*j+1] = v1.x; i[2*j+1] = v1.y;
    }
    fft16_nat<1>(r, i);
    // out[256*d2 + t] at slot REV(d2)

    // ---- store ----
    #pragma unroll
    for (int d2 = 0; d2 < 16; ++d2){
        const int s = REV(d2);
        out2[base + t + 256 * d2] = make_float2(r[s], i[s]);
    }
}

extern "C" void kernel_launch(void* const* d_in, const int* in_sizes, int n_in,
                              void* d_out, int out_size)
{
    const float2* x2 = (const float2*)d_in[0];
    const float2* A2 = (const float2*)d_in[1];
    const float2* D2 = (const float2*)d_in[2];
    float2* out2 = (float2*)d_out;

    const int rows = in_sizes[0] / (4096 * 2);
    afdf_fft9_kernel<<<rows, 256>>>(x2, A2, D2, out2);
}